// round 7
// baseline (speedup 1.0000x reference)
#include <cuda_runtime.h>
#include <math.h>

#define Bx 8
#define Tt 12
#define NN 10000
#define EE 160000
#define OD 64
#define FT 80000 /* flat nodes */

#define NBLK 148
#define NTHR 1024
#define TTHR (NBLK * NTHR) /* 151552 */
#define CHUNK 68           /* 148*68 = 10064 >= NN */

typedef unsigned long long ull;

// ---------------- scratch (__device__ globals; no allocation) ----------------
__device__ float g_xT[FT * 16];       // x^T [f][16] (12 used) for gather
__device__ float g_aggN[FT * 12];     // agg of x over normal edges, [f][12]
__device__ float g_aggC[FT * 12];     // agg of x over causal edges, [f][12]
__device__ float2 g_mflag[NN];        // {degN>0, degC>0}
__device__ int g_rowN[NN + 1];
__device__ int g_rowC[NN + 1];
__device__ int g_colN[EE];
__device__ int g_colC[EE];
__device__ int g_degN[NN];
__device__ int g_degC[NN];
__device__ int g_curN[NN];
__device__ int g_curC[NN];
__device__ int g_psumN[NBLK];
__device__ int g_psumC[NBLK];
__device__ unsigned g_cnt;  // grid-barrier counter; reset by final_kernel
// packed weights: 6 banks x [t:12][pair:32] of {w[d], w[d+32]} (ull = 2 floats)
// banks: 0 Ph1(x->hp) 1 Ph2(a->hp) 2 Pl1(x->lp) 3 Pl2(a->lp) 4 Pl3(c->lp) 5 Pg(x->rp)
__device__ ull g_W[6 * 12 * 32];
__device__ float g_bH0[OD], g_bHm[OD], g_bL0[OD], g_bLm[OD], g_bLc[OD];
// packed epilogue constants: 8 banks x 32 pairs x float4
__device__ float g_Cpk[8 * 32 * 4];

// ---------------- f32x2 helpers ----------------
#define FMA2(d, a, b) asm("fma.rn.f32x2 %0, %1, %2, %0;" : "+l"(d) : "l"(a), "l"(b))
#define ADD2(d, a) asm("add.rn.f32x2 %0, %0, %1;" : "+l"(d) : "l"(a))

__device__ __forceinline__ ull PK2(float lo, float hi) {
    ull r;
    asm("mov.b64 %0, {%1, %2};" : "=l"(r) : "f"(lo), "f"(hi));
    return r;
}
__device__ __forceinline__ void UPK2(float& lo, float& hi, ull v) {
    asm("mov.b64 {%0, %1}, %2;" : "=f"(lo), "=f"(hi) : "l"(v));
}

// ---------------- software grid barrier (all NBLK blocks co-resident) --------
__device__ __forceinline__ void gbar(unsigned phase) {
    __syncthreads();
    if (threadIdx.x == 0) {
        __threadfence();
        atomicAdd(&g_cnt, 1u);
        unsigned target = NBLK * phase;
        while (*(volatile unsigned*)&g_cnt < target) __nanosleep(64);
        __threadfence();
    }
    __syncthreads();
}

// ---------------- K1: persistent pipeline kernel -----------------------------
__global__ void __launch_bounds__(NTHR, 1) pipeline_kernel(
    const float* __restrict__ x, const int* __restrict__ ei, const int* __restrict__ cei,
    const float* __restrict__ W_ht, const float* __restrict__ b_ht,
    const float* __restrict__ W_lt, const float* __restrict__ b_lt,
    const float* __restrict__ Ws_h, const float* __restrict__ Wn_h,
    const float* __restrict__ b_h, const float* __restrict__ Ws_l,
    const float* __restrict__ Wn_l, const float* __restrict__ Wc_l,
    const float* __restrict__ b_l, const float* __restrict__ Whr,
    const float* __restrict__ bhr, const float* __restrict__ Wlr,
    const float* __restrict__ blr, const float* __restrict__ Wg,
    const float* __restrict__ bg, const float* __restrict__ ghn,
    const float* __restrict__ bhn, const float* __restrict__ gln,
    const float* __restrict__ bln, const float* __restrict__ ggn,
    const float* __restrict__ bgn, const float* __restrict__ Wa) {
    const int tid = threadIdx.x;
    const int bid = blockIdx.x;
    const int gtid = bid * NTHR + tid;
    __shared__ int s[256];

    // ===== Phase A: transpose x (gather layout) | count degrees | prep weights
    for (int i = gtid; i < 160832; i += TTHR) {
        if (i < 80000) {
            int b = i / NN;
            int n = i - b * NN;
            float v[12];
#pragma unroll
            for (int t = 0; t < Tt; t++) v[t] = x[((size_t)b * Tt + t) * NN + n];
            float4* dst = (float4*)(g_xT + (size_t)i * 16);
            dst[0] = make_float4(v[0], v[1], v[2], v[3]);
            dst[1] = make_float4(v[4], v[5], v[6], v[7]);
            dst[2] = make_float4(v[8], v[9], v[10], v[11]);
            dst[3] = make_float4(0.f, 0.f, 0.f, 0.f);
        } else if (i < 160000) {
            int q = i - 80000;
            if (q < 40000) {
                int4 v = ((const int4*)(ei + EE))[q];
                atomicAdd(&g_degN[v.x], 1);
                atomicAdd(&g_degN[v.y], 1);
                atomicAdd(&g_degN[v.z], 1);
                atomicAdd(&g_degN[v.w], 1);
            } else {
                int4 v = ((const int4*)(cei + EE))[q - 40000];
                atomicAdd(&g_degC[v.x], 1);
                atomicAdd(&g_degC[v.y], 1);
                atomicAdd(&g_degC[v.z], 1);
                atomicAdd(&g_degC[v.w], 1);
            }
        } else {
            int pid = i - 160000;  // 0..831
            int t = pid >> 6;
            int d = pid & 63;
            int dl = d & 31;
            int hi = d >> 5;
            if (t < Tt) {
                float s1 = 0.f, s2 = 0.f, s3 = 0.f, s4 = 0.f, s5 = 0.f;
                for (int k = 0; k < 64; k++) {
                    float wht = W_ht[t * 64 + k];
                    float wlt = W_lt[t * 64 + k];
                    s1 += wht * (Ws_h[k * 64 + d] + 0.2f * Whr[k * 64 + d]);
                    s2 += wht * Wn_h[k * 64 + d];
                    s3 += wlt * (Ws_l[k * 64 + d] + 0.2f * Wlr[k * 64 + d]);
                    s4 += wlt * Wn_l[k * 64 + d];
                    s5 += wlt * Wc_l[k * 64 + d];
                }
                float* Wf = (float*)g_W;
                int base = (t * 32 + dl) * 2 + hi;
                Wf[base] = s1;
                Wf[768 + base] = s2;
                Wf[1536 + base] = s3;
                Wf[2304 + base] = s4;
                Wf[3072 + base] = s5;
                Wf[3840 + base] = 2.0f * Wg[t * 64 + d];  // x_res = 2x
            } else {
                float bh0 = b_h[d] + 0.2f * bhr[d];
                float bhm = 0.f;
                float bl0 = b_l[d] + 0.2f * blr[d];
                float blm = 0.f, blc = 0.f;
                for (int k = 0; k < 64; k++) {
                    bh0 += b_ht[k] * (Ws_h[k * 64 + d] + 0.2f * Whr[k * 64 + d]);
                    bhm += b_ht[k] * Wn_h[k * 64 + d];
                    bl0 += b_lt[k] * (Ws_l[k * 64 + d] + 0.2f * Wlr[k * 64 + d]);
                    blm += b_lt[k] * Wn_l[k * 64 + d];
                    blc += b_lt[k] * Wc_l[k * 64 + d];
                }
                g_bH0[d] = bh0;
                g_bHm[d] = bhm;
                g_bL0[d] = bl0;
                g_bLm[d] = blm;
                g_bLc[d] = blc;
            }
        }
    }
    gbar(1);

    // ===== Phase B1: per-block partial sums of degrees
    {
        int base = bid * CHUNK;
        if (tid < 68)
            s[tid] = (base + tid < NN) ? g_degN[base + tid] : 0;
        else if (tid < 128)
            s[tid] = 0;
        else if (tid < 196)
            s[tid] = (base + tid - 128 < NN) ? g_degC[base + tid - 128] : 0;
        else if (tid < 256)
            s[tid] = 0;
        __syncthreads();
#pragma unroll
        for (int off = 64; off > 0; off >>= 1) {
            if (tid < off)
                s[tid] += s[tid + off];
            else if (tid >= 128 && tid < 128 + off)
                s[tid] += s[tid + off];
            __syncthreads();
        }
        if (tid == 0) g_psumN[bid] = s[0];
        if (tid == 128) g_psumC[bid] = s[128];
    }
    gbar(2);

    // ===== Phase B2: exclusive scan of 148 partials
    if (bid == 0 && tid < 64) {
        int lane = tid & 31;
        int* p = (tid < 32) ? g_psumN : g_psumC;
        int carry = 0;
        for (int k = 0; k < 5; k++) {
            int i = k * 32 + lane;
            int v = (i < NBLK) ? p[i] : 0;
            int inc = v;
#pragma unroll
            for (int o = 1; o < 32; o <<= 1) {
                int u = __shfl_up_sync(0xffffffffu, inc, o);
                if (lane >= o) inc += u;
            }
            if (i < NBLK) p[i] = carry + inc - v;
            carry += __shfl_sync(0xffffffffu, inc, 31);
        }
    }
    gbar(3);

    // ===== Phase B3: local inclusive scan -> row offsets
    {
        int base = bid * CHUNK;
        if (tid < 68)
            s[tid] = (base + tid < NN) ? g_degN[base + tid] : 0;
        else if (tid < 128)
            s[tid] = 0;
        else if (tid < 196)
            s[tid] = (base + tid - 128 < NN) ? g_degC[base + tid - 128] : 0;
        else if (tid < 256)
            s[tid] = 0;
        __syncthreads();
#pragma unroll
        for (int off = 1; off < 128; off <<= 1) {
            int v = 0;
            if (tid < 256 && (tid & 127) >= off) v = s[tid - off];
            __syncthreads();
            if (tid < 256) s[tid] += v;
            __syncthreads();
        }
        if (tid < 68) {
            int n = base + tid;
            if (n < NN) g_rowN[n + 1] = g_psumN[bid] + s[tid];
        } else if (tid >= 128 && tid < 196) {
            int n = base + tid - 128;
            if (n < NN) g_rowC[n + 1] = g_psumC[bid] + s[tid];
        }
        if (bid == 0 && tid == 0) {
            g_rowN[0] = 0;
            g_rowC[0] = 0;
        }
    }
    gbar(4);

    // ===== Phase C: fill CSR columns | pack epilogue constants
    for (int i = gtid; i < 2 * EE + 32; i += TTHR) {
        if (i < EE) {
            int dd = __ldg(&ei[EE + i]);
            int p = atomicAdd(&g_curN[dd], 1);
            g_colN[g_rowN[dd] + p] = __ldg(&ei[i]);
        } else if (i < 2 * EE) {
            int j = i - EE;
            int dd = __ldg(&cei[EE + j]);
            int p = atomicAdd(&g_curC[dd], 1);
            g_colC[g_rowC[dd] + p] = __ldg(&cei[j]);
        } else {
            int l = i - 2 * EE;  // 0..31
            float4* C = (float4*)g_Cpk;
            C[0 * 32 + l] = make_float4(g_bH0[l], g_bH0[l + 32], g_bHm[l], g_bHm[l + 32]);
            C[1 * 32 + l] = make_float4(g_bL0[l], g_bL0[l + 32], g_bLm[l], g_bLm[l + 32]);
            C[2 * 32 + l] = make_float4(g_bLc[l], g_bLc[l + 32], bg[l], bg[l + 32]);
            C[3 * 32 + l] = make_float4(ghn[l], ghn[l + 32], bhn[l], bhn[l + 32]);
            C[4 * 32 + l] = make_float4(gln[l], gln[l + 32], bln[l], bln[l + 32]);
            C[5 * 32 + l] = make_float4(ggn[l], ggn[l + 32], bgn[l], bgn[l + 32]);
            C[6 * 32 + l] =
                make_float4(Wa[l * 2], Wa[(l + 32) * 2], Wa[l * 2 + 1], Wa[(l + 32) * 2 + 1]);
            C[7 * 32 + l] = make_float4(Wa[(64 + l) * 2], Wa[(96 + l) * 2], Wa[(64 + l) * 2 + 1],
                                        Wa[(96 + l) * 2 + 1]);
        }
    }
    gbar(5);

    // ===== Phase D: gather-aggregate (compact [f][12]) + mflag + cleanup
    for (int idx = gtid; idx < 340000; idx += TTHR) {
        if (idx < 320000) {
            int t = idx & 15;
            if (t >= Tt) continue;
            int n = idx >> 4;
            int causal = (n >= NN);
            if (causal) n -= NN;
            const int* __restrict__ row = causal ? g_rowC : g_rowN;
            const int* __restrict__ col = causal ? g_colC : g_colN;
            float* __restrict__ dst = causal ? g_aggC : g_aggN;
            int rs = row[n], re = row[n + 1];
            float acc[Bx];
#pragma unroll
            for (int b = 0; b < Bx; b++) acc[b] = 0.f;
#pragma unroll 2
            for (int e = rs; e < re; e++) {
                int c = __ldg(&col[e]);
                const float* p = g_xT + c * 16 + t;
#pragma unroll
                for (int b = 0; b < Bx; b++) acc[b] += __ldg(&p[b * NN * 16]);
            }
            float invd = 1.0f / fmaxf((float)(re - rs), 1.0f);
#pragma unroll
            for (int b = 0; b < Bx; b++) dst[(size_t)(b * NN + n) * 12 + t] = acc[b] * invd;
        } else if (idx < 330000) {
            int z = idx - 320000;  // zero deg/cur (int4 granularity)
            int a = z / 2500;
            int r = z - a * 2500;
            int4 zv = make_int4(0, 0, 0, 0);
            if (a == 0)
                ((int4*)g_degN)[r] = zv;
            else if (a == 1)
                ((int4*)g_degC)[r] = zv;
            else if (a == 2)
                ((int4*)g_curN)[r] = zv;
            else
                ((int4*)g_curC)[r] = zv;
        } else {
            int n = idx - 330000;  // mflag from persistent row arrays
            g_mflag[n] = make_float2((g_rowN[n + 1] > g_rowN[n]) ? 1.f : 0.f,
                                     (g_rowC[n + 1] > g_rowC[n]) ? 1.f : 0.f);
        }
    }
}

// ---------------- K2: fused epilogue (4 lanes per node, register-resident) ----
// Block = 256 thr; warp covers 8 nodes; lane group q = lane&3 owns output
// pairs [q*8, q*8+8) of each branch (hp/lp/rp). No smem staging: accumulate,
// LN via 2-round butterfly within the 4-lane group, transform in place, gate,
// fused — all in 24 ull registers per thread.
#define FBLK2 (FT / 64) /* 1250 blocks, 64 nodes each */

__global__ void __launch_bounds__(256, 2) final_kernel(float* __restrict__ out,
                                                       const float* __restrict__ x,
                                                       const float* __restrict__ ba) {
    const int tid = threadIdx.x;
    if (blockIdx.x == 0 && tid == 0) g_cnt = 0;  // reset grid barrier for next replay
    const int lane = tid & 31;
    const int w = tid >> 5;
    const int q = lane & 3;
    const int ni = lane >> 2;

    __shared__ ull sW[2304];    // 6 banks x 12 t x 32 pairs (18.4 KB)
    __shared__ float4 sC[256];  // 8 const banks x 32 pairs  (4 KB)
    for (int i = tid; i < 1152; i += 256)
        ((ulonglong2*)sW)[i] = ((const ulonglong2*)g_W)[i];
    sC[tid] = ((const float4*)g_Cpk)[tid];
    __syncthreads();

    const int f = blockIdx.x * 64 + w * 8 + ni;
    const int b = f / NN;
    const int n = f - b * NN;
    const float ba0 = __ldg(&ba[0]), ba1 = __ldg(&ba[1]);
    const size_t AS = (size_t)Bx * OD * NN;
    const size_t obase = (size_t)(b * OD) * NN + n;

    // ---- init accumulators from packed const banks
    float2 mf = __ldg(&g_mflag[n]);
    ull hp[8], lp[8], rp[8];
#pragma unroll
    for (int j = 0; j < 8; j++) {
        int p = q * 8 + j;
        float4 c0 = sC[p], c1 = sC[32 + p], c2 = sC[64 + p];
        hp[j] = PK2(fmaf(mf.x, c0.z, c0.x), fmaf(mf.x, c0.w, c0.y));
        lp[j] = PK2(fmaf(mf.y, c2.x, fmaf(mf.x, c1.z, c1.x)),
                    fmaf(mf.y, c2.y, fmaf(mf.x, c1.w, c1.y)));
        rp[j] = PK2(c2.z, c2.w);
    }

    // ---- main GEMV: 12 t-steps, features loaded per step, weights from smem
    const ulonglong2* sW2 = (const ulonglong2*)sW;
#pragma unroll
    for (int t = 0; t < Tt; t++) {
        float fx = __ldg(&x[((size_t)b * Tt + t) * NN + n]);
        float fa = __ldg(&g_aggN[(size_t)f * 12 + t]);
        float fc = __ldg(&g_aggC[(size_t)f * 12 + t]);
        ull qx = PK2(fx, fx), qa = PK2(fa, fa), qc = PK2(fc, fc);
        const ulonglong2* r0 = sW2 + t * 16 + q * 4;  // bank stride 192 ulonglong2
#pragma unroll
        for (int u = 0; u < 4; u++) {
            ulonglong2 w0 = r0[u];        // Ph1
            ulonglong2 w1 = r0[192 + u];  // Ph2
            FMA2(hp[2 * u], qx, w0.x);
            FMA2(hp[2 * u + 1], qx, w0.y);
            FMA2(hp[2 * u], qa, w1.x);
            FMA2(hp[2 * u + 1], qa, w1.y);
            ulonglong2 w2 = r0[384 + u];  // Pl1
            ulonglong2 w3 = r0[576 + u];  // Pl2
            ulonglong2 w4 = r0[768 + u];  // Pl3
            FMA2(lp[2 * u], qx, w2.x);
            FMA2(lp[2 * u + 1], qx, w2.y);
            FMA2(lp[2 * u], qa, w3.x);
            FMA2(lp[2 * u + 1], qa, w3.y);
            FMA2(lp[2 * u], qc, w4.x);
            FMA2(lp[2 * u + 1], qc, w4.y);
            ulonglong2 w5 = r0[960 + u];  // Pg
            FMA2(rp[2 * u], qx, w5.x);
            FMA2(rp[2 * u + 1], qx, w5.y);
        }
    }

    // ---- LN stats: thread-partial sums + butterfly over the 4-lane group
    ull aH = 0, aH2 = 0, aL = 0, aL2 = 0, aR = 0, aR2 = 0;
#pragma unroll
    for (int j = 0; j < 8; j++) {
        ADD2(aH, hp[j]);
        FMA2(aH2, hp[j], hp[j]);
        ADD2(aL, lp[j]);
        FMA2(aL2, lp[j], lp[j]);
        ADD2(aR, rp[j]);
        FMA2(aR2, rp[j], rp[j]);
    }
    float u0, u1;
    UPK2(u0, u1, aH);
    float s0 = u0 + u1;
    UPK2(u0, u1, aH2);
    float s1 = u0 + u1;
    UPK2(u0, u1, aL);
    float s2 = u0 + u1;
    UPK2(u0, u1, aL2);
    float s3 = u0 + u1;
    UPK2(u0, u1, aR);
    float s4 = u0 + u1;
    UPK2(u0, u1, aR2);
    float s5 = u0 + u1;
#pragma unroll
    for (int o = 1; o <= 2; o <<= 1) {
        s0 += __shfl_xor_sync(0xffffffffu, s0, o);
        s1 += __shfl_xor_sync(0xffffffffu, s1, o);
        s2 += __shfl_xor_sync(0xffffffffu, s2, o);
        s3 += __shfl_xor_sync(0xffffffffu, s3, o);
        s4 += __shfl_xor_sync(0xffffffffu, s4, o);
        s5 += __shfl_xor_sync(0xffffffffu, s5, o);
    }
    const float inv = 1.0f / 64.0f;
    float mh = s0 * inv, vh = s1 * inv - mh * mh;
    float ml = s2 * inv, vl = s3 * inv - ml * ml;
    float mr = s4 * inv, vr = s5 * inv - mr * mr;
    float rhv = rsqrtf(vh + 1e-5f), rlv = rsqrtf(vl + 1e-5f), rrv = rsqrtf(vr + 1e-5f);

    // ---- e1: LN + activations, write high/low, keep in regs, gate partials
    float z0 = 0.f, z1 = 0.f;
#pragma unroll 2
    for (int j = 0; j < 8; j++) {
        int p = q * 8 + j;
        float4 c3 = sC[96 + p], c4 = sC[128 + p], c5 = sC[160 + p];
        float4 c6 = sC[192 + p], c7 = sC[224 + p];
        float hl, hh, ll, lh, rl, rh;
        UPK2(hl, hh, hp[j]);
        UPK2(ll, lh, lp[j]);
        UPK2(rl, rh, rp[j]);
        float highl = fmaf((hl - mh) * rhv, c3.x, c3.z);
        float highh = fmaf((hh - mh) * rhv, c3.y, c3.w);
        highl = (highl >= 0.f) ? highl : 0.1f * highl;
        highh = (highh >= 0.f) ? highh : 0.1f * highh;
        float lwl = fmaf((ll - ml) * rlv, c4.x, c4.z);
        float lwh = fmaf((lh - ml) * rlv, c4.y, c4.w);
        float lowl = 0.5f * lwl * (1.0f + erff(lwl * 0.70710678118654752f));
        float lowh = 0.5f * lwh * (1.0f + erff(lwh * 0.70710678118654752f));
        float resl = fmaf((rl - mr) * rrv, c5.x, c5.z);
        float resh = fmaf((rh - mr) * rrv, c5.y, c5.w);
        z0 += highl * c6.x + highh * c6.y + lowl * c7.x + lowh * c7.y;
        z1 += highl * c6.z + highh * c6.w + lowl * c7.z + lowh * c7.w;
        size_t bb = obase + (size_t)p * NN;
        out[AS + bb] = highl;
        out[AS + bb + (size_t)32 * NN] = highh;
        out[2 * AS + bb] = lowl;
        out[2 * AS + bb + (size_t)32 * NN] = lowh;
        hp[j] = PK2(highl, highh);
        lp[j] = PK2(lowl, lowh);
        rp[j] = PK2(resl, resh);
    }
#pragma unroll
    for (int o = 1; o <= 2; o <<= 1) {
        z0 += __shfl_xor_sync(0xffffffffu, z0, o);
        z1 += __shfl_xor_sync(0xffffffffu, z1, o);
    }
    float a0 = 1.0f / (1.0f + expf((z1 + ba1) - (z0 + ba0)));
    float a1 = 1.0f - a0;

    // ---- e2: fused output straight from registers
#pragma unroll 2
    for (int j = 0; j < 8; j++) {
        int p = q * 8 + j;
        float hl, hh, ll, lh, rl, rh;
        UPK2(hl, hh, hp[j]);
        UPK2(ll, lh, lp[j]);
        UPK2(rl, rh, rp[j]);
        float fl = fmaf(a0, hl, a1 * ll) + 0.3f * (hl + ll) + 0.1f * rl;
        float fh = fmaf(a0, hh, a1 * lh) + 0.3f * (hh + lh) + 0.1f * rh;
        size_t bb = obase + (size_t)p * NN;
        out[bb] = fl;
        out[bb + (size_t)32 * NN] = fh;
    }
}

// ---------------- launch ------------------------------------------------------

extern "C" void kernel_launch(void* const* d_in, const int* in_sizes, int n_in, void* d_out,
                              int out_size) {
    const float* x = (const float*)d_in[0];
    const int* ei = (const int*)d_in[1];
    const int* cei = (const int*)d_in[2];
    const float* W_ht = (const float*)d_in[3];
    const float* b_ht = (const float*)d_in[4];
    const float* W_lt = (const float*)d_in[5];
    const float* b_lt = (const float*)d_in[6];
    const float* Ws_h = (const float*)d_in[7];
    const float* Wn_h = (const float*)d_in[8];
    const float* b_h = (const float*)d_in[9];
    const float* Ws_l = (const float*)d_in[10];
    const float* Wn_l = (const float*)d_in[11];
    const float* Wc_l = (const float*)d_in[12];
    const float* b_l = (const float*)d_in[13];
    const float* Whr = (const float*)d_in[14];
    const float* bhr = (const float*)d_in[15];
    const float* Wlr = (const float*)d_in[16];
    const float* blr = (const float*)d_in[17];
    const float* ghn = (const float*)d_in[18];
    const float* bhn = (const float*)d_in[19];
    const float* gln = (const float*)d_in[20];
    const float* bln = (const float*)d_in[21];
    const float* Wa = (const float*)d_in[22];
    const float* ba = (const float*)d_in[23];
    const float* Wg = (const float*)d_in[24];
    const float* bg = (const float*)d_in[25];
    const float* ggn = (const float*)d_in[26];
    const float* bgn = (const float*)d_in[27];
    float* out = (float*)d_out;

    pipeline_kernel<<<NBLK, NTHR>>>(x, ei, cei, W_ht, b_ht, W_lt, b_lt, Ws_h, Wn_h, b_h, Ws_l,
                                    Wn_l, Wc_l, b_l, Whr, bhr, Wlr, blr, Wg, bg, ghn, bhn, gln,
                                    bln, ggn, bgn, Wa);
    final_kernel<<<FBLK2, 256>>>(out, x, ba);
}

// round 8
// speedup vs baseline: 1.5774x; 1.5774x over previous
#include <cuda_runtime.h>
#include <math.h>

#define Bx 8
#define Tt 12
#define NN 10000
#define EE 160000
#define OD 64
#define FT 80000 /* flat nodes */

#define NBLK 148
#define NTHR 1024
#define TTHR (NBLK * NTHR) /* 151552 */
#define CHUNK 68           /* 148*68 = 10064 >= NN */

typedef unsigned long long ull;

// ---------------- scratch (__device__ globals; no allocation) ----------------
__device__ float g_xT[FT * 16];    // x^T [f][16] (12 used) for gather
__device__ float g_aggN[FT * 12];  // agg of x over normal edges, [f][12]
__device__ float g_aggC[FT * 12];  // agg of x over causal edges, [f][12]
__device__ float2 g_mflag[NN];     // {degN>0, degC>0}
__device__ int g_rowN[NN + 1];
__device__ int g_rowC[NN + 1];
__device__ int g_colN[EE];
__device__ int g_colC[EE];
__device__ int g_degN[NN];
__device__ int g_degC[NN];
__device__ int g_curN[NN];
__device__ int g_curC[NN];
__device__ int g_psumN[NBLK];
__device__ int g_psumC[NBLK];
__device__ unsigned g_cnt;  // grid-barrier counter; reset by final_kernel
// packed weights: 6 banks x [t:12][pair:32] of {w[d], w[d+32]} (ull = 2 floats)
// banks: 0 Ph1(x->hp) 1 Ph2(a->hp) 2 Pl1(x->lp) 3 Pl2(a->lp) 4 Pl3(c->lp) 5 Pg(x->rp)
__device__ ull g_W[6 * 12 * 32];
__device__ float g_bH0[OD], g_bHm[OD], g_bL0[OD], g_bLm[OD], g_bLc[OD];
// packed epilogue constants: 8 banks x 32 pairs x float4
__device__ float g_Cpk[8 * 32 * 4];

// ---------------- f32x2 helpers ----------------
#define FMA2(d, a, b) asm("fma.rn.f32x2 %0, %1, %2, %0;" : "+l"(d) : "l"(a), "l"(b))
#define ADD2(d, a) asm("add.rn.f32x2 %0, %0, %1;" : "+l"(d) : "l"(a))

__device__ __forceinline__ ull PK2(float lo, float hi) {
    ull r;
    asm("mov.b64 %0, {%1, %2};" : "=l"(r) : "f"(lo), "f"(hi));
    return r;
}
__device__ __forceinline__ void UPK2(float& lo, float& hi, ull v) {
    asm("mov.b64 {%0, %1}, %2;" : "=f"(lo), "=f"(hi) : "l"(v));
}

// ---------------- software grid barrier (all NBLK blocks co-resident) --------
__device__ __forceinline__ void gbar(unsigned phase) {
    __syncthreads();
    if (threadIdx.x == 0) {
        __threadfence();
        atomicAdd(&g_cnt, 1u);
        unsigned target = NBLK * phase;
        while (*(volatile unsigned*)&g_cnt < target) __nanosleep(64);
        __threadfence();
    }
    __syncthreads();
}

// ---------------- K1: persistent pipeline kernel -----------------------------
__global__ void __launch_bounds__(NTHR, 1) pipeline_kernel(
    const float* __restrict__ x, const int* __restrict__ ei, const int* __restrict__ cei,
    const float* __restrict__ W_ht, const float* __restrict__ b_ht,
    const float* __restrict__ W_lt, const float* __restrict__ b_lt,
    const float* __restrict__ Ws_h, const float* __restrict__ Wn_h,
    const float* __restrict__ b_h, const float* __restrict__ Ws_l,
    const float* __restrict__ Wn_l, const float* __restrict__ Wc_l,
    const float* __restrict__ b_l, const float* __restrict__ Whr,
    const float* __restrict__ bhr, const float* __restrict__ Wlr,
    const float* __restrict__ blr, const float* __restrict__ Wg,
    const float* __restrict__ bg, const float* __restrict__ ghn,
    const float* __restrict__ bhn, const float* __restrict__ gln,
    const float* __restrict__ bln, const float* __restrict__ ggn,
    const float* __restrict__ bgn, const float* __restrict__ Wa) {
    const int tid = threadIdx.x;
    const int bid = blockIdx.x;
    const int gtid = bid * NTHR + tid;
    __shared__ int s[256];

    // ===== Phase A: transpose x (gather layout) | count degrees | prep weights
    for (int i = gtid; i < 160832; i += TTHR) {
        if (i < 80000) {
            int b = i / NN;
            int n = i - b * NN;
            float v[12];
#pragma unroll
            for (int t = 0; t < Tt; t++) v[t] = x[((size_t)b * Tt + t) * NN + n];
            float4* dst = (float4*)(g_xT + (size_t)i * 16);
            dst[0] = make_float4(v[0], v[1], v[2], v[3]);
            dst[1] = make_float4(v[4], v[5], v[6], v[7]);
            dst[2] = make_float4(v[8], v[9], v[10], v[11]);
            dst[3] = make_float4(0.f, 0.f, 0.f, 0.f);
        } else if (i < 160000) {
            int q = i - 80000;
            if (q < 40000) {
                int4 v = ((const int4*)(ei + EE))[q];
                atomicAdd(&g_degN[v.x], 1);
                atomicAdd(&g_degN[v.y], 1);
                atomicAdd(&g_degN[v.z], 1);
                atomicAdd(&g_degN[v.w], 1);
            } else {
                int4 v = ((const int4*)(cei + EE))[q - 40000];
                atomicAdd(&g_degC[v.x], 1);
                atomicAdd(&g_degC[v.y], 1);
                atomicAdd(&g_degC[v.z], 1);
                atomicAdd(&g_degC[v.w], 1);
            }
        } else {
            int pid = i - 160000;  // 0..831
            int t = pid >> 6;
            int d = pid & 63;
            int dl = d & 31;
            int hi = d >> 5;
            if (t < Tt) {
                float s1 = 0.f, s2 = 0.f, s3 = 0.f, s4 = 0.f, s5 = 0.f;
                for (int k = 0; k < 64; k++) {
                    float wht = W_ht[t * 64 + k];
                    float wlt = W_lt[t * 64 + k];
                    s1 += wht * (Ws_h[k * 64 + d] + 0.2f * Whr[k * 64 + d]);
                    s2 += wht * Wn_h[k * 64 + d];
                    s3 += wlt * (Ws_l[k * 64 + d] + 0.2f * Wlr[k * 64 + d]);
                    s4 += wlt * Wn_l[k * 64 + d];
                    s5 += wlt * Wc_l[k * 64 + d];
                }
                float* Wf = (float*)g_W;
                int base = (t * 32 + dl) * 2 + hi;
                Wf[base] = s1;
                Wf[768 + base] = s2;
                Wf[1536 + base] = s3;
                Wf[2304 + base] = s4;
                Wf[3072 + base] = s5;
                Wf[3840 + base] = 2.0f * Wg[t * 64 + d];  // x_res = 2x
            } else {
                float bh0 = b_h[d] + 0.2f * bhr[d];
                float bhm = 0.f;
                float bl0 = b_l[d] + 0.2f * blr[d];
                float blm = 0.f, blc = 0.f;
                for (int k = 0; k < 64; k++) {
                    bh0 += b_ht[k] * (Ws_h[k * 64 + d] + 0.2f * Whr[k * 64 + d]);
                    bhm += b_ht[k] * Wn_h[k * 64 + d];
                    bl0 += b_lt[k] * (Ws_l[k * 64 + d] + 0.2f * Wlr[k * 64 + d]);
                    blm += b_lt[k] * Wn_l[k * 64 + d];
                    blc += b_lt[k] * Wc_l[k * 64 + d];
                }
                g_bH0[d] = bh0;
                g_bHm[d] = bhm;
                g_bL0[d] = bl0;
                g_bLm[d] = blm;
                g_bLc[d] = blc;
            }
        }
    }
    gbar(1);

    // ===== Phase B1: per-block partial sums of degrees
    {
        int base = bid * CHUNK;
        if (tid < 68)
            s[tid] = (base + tid < NN) ? g_degN[base + tid] : 0;
        else if (tid < 128)
            s[tid] = 0;
        else if (tid < 196)
            s[tid] = (base + tid - 128 < NN) ? g_degC[base + tid - 128] : 0;
        else if (tid < 256)
            s[tid] = 0;
        __syncthreads();
#pragma unroll
        for (int off = 64; off > 0; off >>= 1) {
            if (tid < off)
                s[tid] += s[tid + off];
            else if (tid >= 128 && tid < 128 + off)
                s[tid] += s[tid + off];
            __syncthreads();
        }
        if (tid == 0) g_psumN[bid] = s[0];
        if (tid == 128) g_psumC[bid] = s[128];
    }
    gbar(2);

    // ===== Phase B2: exclusive scan of 148 partials
    if (bid == 0 && tid < 64) {
        int lane = tid & 31;
        int* p = (tid < 32) ? g_psumN : g_psumC;
        int carry = 0;
        for (int k = 0; k < 5; k++) {
            int i = k * 32 + lane;
            int v = (i < NBLK) ? p[i] : 0;
            int inc = v;
#pragma unroll
            for (int o = 1; o < 32; o <<= 1) {
                int u = __shfl_up_sync(0xffffffffu, inc, o);
                if (lane >= o) inc += u;
            }
            if (i < NBLK) p[i] = carry + inc - v;
            carry += __shfl_sync(0xffffffffu, inc, 31);
        }
    }
    gbar(3);

    // ===== Phase B3: local inclusive scan -> row offsets
    {
        int base = bid * CHUNK;
        if (tid < 68)
            s[tid] = (base + tid < NN) ? g_degN[base + tid] : 0;
        else if (tid < 128)
            s[tid] = 0;
        else if (tid < 196)
            s[tid] = (base + tid - 128 < NN) ? g_degC[base + tid - 128] : 0;
        else if (tid < 256)
            s[tid] = 0;
        __syncthreads();
#pragma unroll
        for (int off = 1; off < 128; off <<= 1) {
            int v = 0;
            if (tid < 256 && (tid & 127) >= off) v = s[tid - off];
            __syncthreads();
            if (tid < 256) s[tid] += v;
            __syncthreads();
        }
        if (tid < 68) {
            int n = base + tid;
            if (n < NN) g_rowN[n + 1] = g_psumN[bid] + s[tid];
        } else if (tid >= 128 && tid < 196) {
            int n = base + tid - 128;
            if (n < NN) g_rowC[n + 1] = g_psumC[bid] + s[tid];
        }
        if (bid == 0 && tid == 0) {
            g_rowN[0] = 0;
            g_rowC[0] = 0;
        }
    }
    gbar(4);

    // ===== Phase C: fill CSR columns | pack epilogue constants
    for (int i = gtid; i < 2 * EE + 32; i += TTHR) {
        if (i < EE) {
            int dd = __ldg(&ei[EE + i]);
            int p = atomicAdd(&g_curN[dd], 1);
            g_colN[g_rowN[dd] + p] = __ldg(&ei[i]);
        } else if (i < 2 * EE) {
            int j = i - EE;
            int dd = __ldg(&cei[EE + j]);
            int p = atomicAdd(&g_curC[dd], 1);
            g_colC[g_rowC[dd] + p] = __ldg(&cei[j]);
        } else {
            int l = i - 2 * EE;  // 0..31
            float4* C = (float4*)g_Cpk;
            C[0 * 32 + l] = make_float4(g_bH0[l], g_bH0[l + 32], g_bHm[l], g_bHm[l + 32]);
            C[1 * 32 + l] = make_float4(g_bL0[l], g_bL0[l + 32], g_bLm[l], g_bLm[l + 32]);
            C[2 * 32 + l] = make_float4(g_bLc[l], g_bLc[l + 32], bg[l], bg[l + 32]);
            C[3 * 32 + l] = make_float4(ghn[l], ghn[l + 32], bhn[l], bhn[l + 32]);
            C[4 * 32 + l] = make_float4(gln[l], gln[l + 32], bln[l], bln[l + 32]);
            C[5 * 32 + l] = make_float4(ggn[l], ggn[l + 32], bgn[l], bgn[l + 32]);
            C[6 * 32 + l] =
                make_float4(Wa[l * 2], Wa[(l + 32) * 2], Wa[l * 2 + 1], Wa[(l + 32) * 2 + 1]);
            C[7 * 32 + l] = make_float4(Wa[(64 + l) * 2], Wa[(96 + l) * 2], Wa[(64 + l) * 2 + 1],
                                        Wa[(96 + l) * 2 + 1]);
        }
    }
    gbar(5);

    // ===== Phase D: gather-aggregate (compact [f][12]) + mflag + cleanup
    for (int idx = gtid; idx < 340000; idx += TTHR) {
        if (idx < 320000) {
            int t = idx & 15;
            if (t >= Tt) continue;
            int n = idx >> 4;
            int causal = (n >= NN);
            if (causal) n -= NN;
            const int* __restrict__ row = causal ? g_rowC : g_rowN;
            const int* __restrict__ col = causal ? g_colC : g_colN;
            float* __restrict__ dst = causal ? g_aggC : g_aggN;
            int rs = row[n], re = row[n + 1];
            float acc[Bx];
#pragma unroll
            for (int b = 0; b < Bx; b++) acc[b] = 0.f;
#pragma unroll 2
            for (int e = rs; e < re; e++) {
                int c = __ldg(&col[e]);
                const float* p = g_xT + c * 16 + t;
#pragma unroll
                for (int b = 0; b < Bx; b++) acc[b] += __ldg(&p[b * NN * 16]);
            }
            float invd = 1.0f / fmaxf((float)(re - rs), 1.0f);
#pragma unroll
            for (int b = 0; b < Bx; b++) dst[(size_t)(b * NN + n) * 12 + t] = acc[b] * invd;
        } else if (idx < 330000) {
            int z = idx - 320000;  // zero deg/cur (int4 granularity)
            int a = z / 2500;
            int r = z - a * 2500;
            int4 zv = make_int4(0, 0, 0, 0);
            if (a == 0)
                ((int4*)g_degN)[r] = zv;
            else if (a == 1)
                ((int4*)g_degC)[r] = zv;
            else if (a == 2)
                ((int4*)g_curN)[r] = zv;
            else
                ((int4*)g_curC)[r] = zv;
        } else {
            int n = idx - 330000;  // mflag from persistent row arrays
            g_mflag[n] = make_float2((g_rowN[n + 1] > g_rowN[n]) ? 1.f : 0.f,
                                     (g_rowC[n + 1] > g_rowC[n]) ? 1.f : 0.f);
        }
    }
}

// ---------------- K2: fused epilogue (thread-per-node, two-pass, no staging) --
// 128 thr/block, thread = one flat node. All weight LDS are warp-uniform
// (broadcast, 1 wavefront). Pass A: stats only. Pass B: recompute hp/lp,
// transform, write high/low, gate partials. Pass C: recompute rp, read back
// high/low (same-thread, L2-hot), fuse.
#define FB3 (FT / 128) /* 625 blocks */

__global__ void __launch_bounds__(128, 4) final_kernel(float* __restrict__ out,
                                                       const float* __restrict__ x,
                                                       const float* __restrict__ ba) {
    const int tid = threadIdx.x;
    if (blockIdx.x == 0 && tid == 0) g_cnt = 0;  // reset grid barrier for next replay

    __shared__ ull sW[2304];    // 6 banks x 12 t x 32 pairs (18.4 KB)
    __shared__ float4 sC[256];  // 8 const banks x 32 pairs  (4 KB)
#pragma unroll
    for (int i = 0; i < 9; i++)
        ((ulonglong2*)sW)[tid + i * 128] = ((const ulonglong2*)g_W)[tid + i * 128];
    sC[tid] = ((const float4*)g_Cpk)[tid];
    sC[tid + 128] = ((const float4*)g_Cpk)[tid + 128];
    __syncthreads();

    const int f = blockIdx.x * 128 + tid;
    const int b = f / NN;
    const int n = f - b * NN;
    const float ba0 = __ldg(&ba[0]), ba1 = __ldg(&ba[1]);
    const size_t AS = (size_t)Bx * OD * NN;
    const size_t obase = (size_t)(b * OD) * NN + n;

    // ---- features (held in registers across all passes)
    float vx[12], va[12], vc[12];
#pragma unroll
    for (int t = 0; t < Tt; t++) vx[t] = __ldg(&x[((size_t)b * Tt + t) * NN + n]);
    {
        const float4* pa = (const float4*)(g_aggN + (size_t)f * 12);
        const float4* pc = (const float4*)(g_aggC + (size_t)f * 12);
#pragma unroll
        for (int k = 0; k < 3; k++) {
            float4 a4 = __ldg(&pa[k]);
            float4 c4 = __ldg(&pc[k]);
            va[4 * k] = a4.x;
            va[4 * k + 1] = a4.y;
            va[4 * k + 2] = a4.z;
            va[4 * k + 3] = a4.w;
            vc[4 * k] = c4.x;
            vc[4 * k + 1] = c4.y;
            vc[4 * k + 2] = c4.z;
            vc[4 * k + 3] = c4.w;
        }
    }
    float2 mf = __ldg(&g_mflag[n]);
    const ull pkm = PK2(mf.x, mf.x), pkmc = PK2(mf.y, mf.y);

    // ================= pass A: stats only =================
    ull aH = 0, aH2 = 0, aL = 0, aL2 = 0, aR = 0, aR2 = 0;
#pragma unroll 1
    for (int c = 0; c < 4; c++) {  // hp: banks 0,1
        int p0 = c * 8;
        ull acc[8];
#pragma unroll
        for (int j = 0; j < 8; j++) {
            float4 c0 = sC[p0 + j];
            acc[j] = PK2(c0.x, c0.y);
            FMA2(acc[j], pkm, PK2(c0.z, c0.w));
        }
#pragma unroll
        for (int t = 0; t < Tt; t++) {
            ull qx = PK2(vx[t], vx[t]), qa = PK2(va[t], va[t]);
            const ull* w0 = sW + t * 32 + p0;
#pragma unroll
            for (int j = 0; j < 8; j++) {
                FMA2(acc[j], qx, w0[j]);
                FMA2(acc[j], qa, w0[384 + j]);
            }
        }
#pragma unroll
        for (int j = 0; j < 8; j++) {
            ADD2(aH, acc[j]);
            FMA2(aH2, acc[j], acc[j]);
        }
    }
#pragma unroll 1
    for (int c = 0; c < 4; c++) {  // lp: banks 2,3,4
        int p0 = c * 8;
        ull acc[8];
#pragma unroll
        for (int j = 0; j < 8; j++) {
            float4 c1 = sC[32 + p0 + j];
            float4 c2 = sC[64 + p0 + j];
            acc[j] = PK2(c1.x, c1.y);
            FMA2(acc[j], pkm, PK2(c1.z, c1.w));
            FMA2(acc[j], pkmc, PK2(c2.x, c2.y));
        }
#pragma unroll
        for (int t = 0; t < Tt; t++) {
            ull qx = PK2(vx[t], vx[t]), qa = PK2(va[t], va[t]), qc = PK2(vc[t], vc[t]);
            const ull* w2 = sW + 768 + t * 32 + p0;
#pragma unroll
            for (int j = 0; j < 8; j++) {
                FMA2(acc[j], qx, w2[j]);
                FMA2(acc[j], qa, w2[384 + j]);
                FMA2(acc[j], qc, w2[768 + j]);
            }
        }
#pragma unroll
        for (int j = 0; j < 8; j++) {
            ADD2(aL, acc[j]);
            FMA2(aL2, acc[j], acc[j]);
        }
    }
#pragma unroll 1
    for (int c = 0; c < 4; c++) {  // rp: bank 5
        int p0 = c * 8;
        ull acc[8];
#pragma unroll
        for (int j = 0; j < 8; j++) {
            float4 c2 = sC[64 + p0 + j];
            acc[j] = PK2(c2.z, c2.w);
        }
#pragma unroll
        for (int t = 0; t < Tt; t++) {
            ull qx = PK2(vx[t], vx[t]);
            const ull* w5 = sW + 1920 + t * 32 + p0;
#pragma unroll
            for (int j = 0; j < 8; j++) FMA2(acc[j], qx, w5[j]);
        }
#pragma unroll
        for (int j = 0; j < 8; j++) {
            ADD2(aR, acc[j]);
            FMA2(aR2, acc[j], acc[j]);
        }
    }
    const float inv = 1.0f / 64.0f;
    float u0, u1;
    UPK2(u0, u1, aH);
    float mh = (u0 + u1) * inv;
    UPK2(u0, u1, aH2);
    float vh = (u0 + u1) * inv - mh * mh;
    UPK2(u0, u1, aL);
    float ml = (u0 + u1) * inv;
    UPK2(u0, u1, aL2);
    float vl = (u0 + u1) * inv - ml * ml;
    UPK2(u0, u1, aR);
    float mr = (u0 + u1) * inv;
    UPK2(u0, u1, aR2);
    float vr = (u0 + u1) * inv - mr * mr;
    float rhv = rsqrtf(vh + 1e-5f), rlv = rsqrtf(vl + 1e-5f), rrv = rsqrtf(vr + 1e-5f);

    // ================= pass B: high & low (write + gate partials) =============
    float z0 = 0.f, z1 = 0.f;
#pragma unroll 1
    for (int c = 0; c < 4; c++) {  // hp
        int p0 = c * 8;
        ull acc[8];
#pragma unroll
        for (int j = 0; j < 8; j++) {
            float4 c0 = sC[p0 + j];
            acc[j] = PK2(c0.x, c0.y);
            FMA2(acc[j], pkm, PK2(c0.z, c0.w));
        }
#pragma unroll
        for (int t = 0; t < Tt; t++) {
            ull qx = PK2(vx[t], vx[t]), qa = PK2(va[t], va[t]);
            const ull* w0 = sW + t * 32 + p0;
#pragma unroll
            for (int j = 0; j < 8; j++) {
                FMA2(acc[j], qx, w0[j]);
                FMA2(acc[j], qa, w0[384 + j]);
            }
        }
#pragma unroll
        for (int j = 0; j < 8; j++) {
            int p = p0 + j;
            float4 c3 = sC[96 + p], c6 = sC[192 + p];
            float hl, hh;
            UPK2(hl, hh, acc[j]);
            float highl = fmaf((hl - mh) * rhv, c3.x, c3.z);
            float highh = fmaf((hh - mh) * rhv, c3.y, c3.w);
            highl = (highl >= 0.f) ? highl : 0.1f * highl;
            highh = (highh >= 0.f) ? highh : 0.1f * highh;
            z0 += highl * c6.x + highh * c6.y;
            z1 += highl * c6.z + highh * c6.w;
            out[AS + obase + (size_t)p * NN] = highl;
            out[AS + obase + (size_t)(p + 32) * NN] = highh;
        }
    }
#pragma unroll 1
    for (int c = 0; c < 4; c++) {  // lp
        int p0 = c * 8;
        ull acc[8];
#pragma unroll
        for (int j = 0; j < 8; j++) {
            float4 c1 = sC[32 + p0 + j];
            float4 c2 = sC[64 + p0 + j];
            acc[j] = PK2(c1.x, c1.y);
            FMA2(acc[j], pkm, PK2(c1.z, c1.w));
            FMA2(acc[j], pkmc, PK2(c2.x, c2.y));
        }
#pragma unroll
        for (int t = 0; t < Tt; t++) {
            ull qx = PK2(vx[t], vx[t]), qa = PK2(va[t], va[t]), qc = PK2(vc[t], vc[t]);
            const ull* w2 = sW + 768 + t * 32 + p0;
#pragma unroll
            for (int j = 0; j < 8; j++) {
                FMA2(acc[j], qx, w2[j]);
                FMA2(acc[j], qa, w2[384 + j]);
                FMA2(acc[j], qc, w2[768 + j]);
            }
        }
#pragma unroll
        for (int j = 0; j < 8; j++) {
            int p = p0 + j;
            float4 c4 = sC[128 + p], c7 = sC[224 + p];
            float ll, lh;
            UPK2(ll, lh, acc[j]);
            float lwl = fmaf((ll - ml) * rlv, c4.x, c4.z);
            float lwh = fmaf((lh - ml) * rlv, c4.y, c4.w);
            float lowl = 0.5f * lwl * (1.0f + erff(lwl * 0.70710678118654752f));
            float lowh = 0.5f * lwh * (1.0f + erff(lwh * 0.70710678118654752f));
            z0 += lowl * c7.x + lowh * c7.y;
            z1 += lowl * c7.z + lowh * c7.w;
            out[2 * AS + obase + (size_t)p * NN] = lowl;
            out[2 * AS + obase + (size_t)(p + 32) * NN] = lowh;
        }
    }
    float a0 = 1.0f / (1.0f + expf((z1 + ba1) - (z0 + ba0)));
    float a1 = 1.0f - a0;

    // ================= pass C: res (recompute) + read-back + fuse =============
#pragma unroll 1
    for (int c = 0; c < 4; c++) {  // rp
        int p0 = c * 8;
        ull acc[8];
#pragma unroll
        for (int j = 0; j < 8; j++) {
            float4 c2 = sC[64 + p0 + j];
            acc[j] = PK2(c2.z, c2.w);
        }
#pragma unroll
        for (int t = 0; t < Tt; t++) {
            ull qx = PK2(vx[t], vx[t]);
            const ull* w5 = sW + 1920 + t * 32 + p0;
#pragma unroll
            for (int j = 0; j < 8; j++) FMA2(acc[j], qx, w5[j]);
        }
#pragma unroll
        for (int j = 0; j < 8; j++) {
            int p = p0 + j;
            float4 c5 = sC[160 + p];
            float rl, rh;
            UPK2(rl, rh, acc[j]);
            float resl = fmaf((rl - mr) * rrv, c5.x, c5.z);
            float resh = fmaf((rh - mr) * rrv, c5.y, c5.w);
            size_t bl = obase + (size_t)p * NN;
            size_t bh = obase + (size_t)(p + 32) * NN;
            float hl = out[AS + bl], hh = out[AS + bh];
            float ll = out[2 * AS + bl], lh = out[2 * AS + bh];
            float fl = fmaf(a0, hl, a1 * ll) + 0.3f * (hl + ll) + 0.1f * resl;
            float fh = fmaf(a0, hh, a1 * lh) + 0.3f * (hh + lh) + 0.1f * resh;
            out[bl] = fl;
            out[bh] = fh;
        }
    }
}

// ---------------- launch ------------------------------------------------------

extern "C" void kernel_launch(void* const* d_in, const int* in_sizes, int n_in, void* d_out,
                              int out_size) {
    const float* x = (const float*)d_in[0];
    const int* ei = (const int*)d_in[1];
    const int* cei = (const int*)d_in[2];
    const float* W_ht = (const float*)d_in[3];
    const float* b_ht = (const float*)d_in[4];
    const float* W_lt = (const float*)d_in[5];
    const float* b_lt = (const float*)d_in[6];
    const float* Ws_h = (const float*)d_in[7];
    const float* Wn_h = (const float*)d_in[8];
    const float* b_h = (const float*)d_in[9];
    const float* Ws_l = (const float*)d_in[10];
    const float* Wn_l = (const float*)d_in[11];
    const float* Wc_l = (const float*)d_in[12];
    const float* b_l = (const float*)d_in[13];
    const float* Whr = (const float*)d_in[14];
    const float* bhr = (const float*)d_in[15];
    const float* Wlr = (const float*)d_in[16];
    const float* blr = (const float*)d_in[17];
    const float* ghn = (const float*)d_in[18];
    const float* bhn = (const float*)d_in[19];
    const float* gln = (const float*)d_in[20];
    const float* bln = (const float*)d_in[21];
    const float* Wa = (const float*)d_in[22];
    const float* ba = (const float*)d_in[23];
    const float* Wg = (const float*)d_in[24];
    const float* bg = (const float*)d_in[25];
    const float* ggn = (const float*)d_in[26];
    const float* bgn = (const float*)d_in[27];
    float* out = (float*)d_out;

    pipeline_kernel<<<NBLK, NTHR>>>(x, ei, cei, W_ht, b_ht, W_lt, b_lt, Ws_h, Wn_h, b_h, Ws_l,
                                    Wn_l, Wc_l, b_l, Whr, bhr, Wlr, blr, Wg, bg, ghn, bhn, gln,
                                    bln, ggn, bgn, Wa);
    final_kernel<<<FB3, 128>>>(out, x, ba);
}

// round 9
// speedup vs baseline: 1.8270x; 1.1583x over previous
#include <cuda_runtime.h>
#include <math.h>

#define Bx 8
#define Tt 12
#define NN 10000
#define EE 160000
#define OD 64
#define FT 80000 /* flat nodes */

#define NBLK 148
#define NTHR 1024
#define TTHR (NBLK * NTHR) /* 151552 */
#define CHUNK 68           /* 148*68 = 10064 >= NN */

typedef unsigned long long ull;

// ---------------- scratch (__device__ globals; no allocation) ----------------
__device__ float g_xT[FT * 16];    // x^T [f][16] (12 used) for gather
__device__ float g_aggN[FT * 12];  // agg of x over normal edges, [f][12]
__device__ float g_aggC[FT * 12];  // agg of x over causal edges, [f][12]
__device__ float2 g_mflag[NN];     // {degN>0, degC>0}
__device__ int g_rowN[NN + 1];
__device__ int g_rowC[NN + 1];
__device__ int g_colN[EE];
__device__ int g_colC[EE];
__device__ int g_degN[NN];
__device__ int g_degC[NN];
__device__ int g_curN[NN];
__device__ int g_curC[NN];
__device__ int g_psumN[NBLK];
__device__ int g_psumC[NBLK];
__device__ unsigned g_cnt;  // grid-barrier counter; reset by final_kernel
// packed weights: 6 banks x [t:12][pair:32] of {w[d], w[d+32]} (ull = 2 floats)
// banks: 0 Ph1(x->hp) 1 Ph2(a->hp) 2 Pl1(x->lp) 3 Pl2(a->lp) 4 Pl3(c->lp) 5 Pg(x->rp)
__device__ ull g_W[6 * 12 * 32];
__device__ float g_bH0[OD], g_bHm[OD], g_bL0[OD], g_bLm[OD], g_bLc[OD];
// packed epilogue constants: 8 banks x 32 pairs x float4
__device__ float g_Cpk[8 * 32 * 4];

// ---------------- f32x2 helpers ----------------
#define FMA2(d, a, b) asm("fma.rn.f32x2 %0, %1, %2, %0;" : "+l"(d) : "l"(a), "l"(b))
#define ADD2(d, a) asm("add.rn.f32x2 %0, %0, %1;" : "+l"(d) : "l"(a))

__device__ __forceinline__ ull PK2(float lo, float hi) {
    ull r;
    asm("mov.b64 %0, {%1, %2};" : "=l"(r) : "f"(lo), "f"(hi));
    return r;
}
__device__ __forceinline__ void UPK2(float& lo, float& hi, ull v) {
    asm("mov.b64 {%0, %1}, %2;" : "=f"(lo), "=f"(hi) : "l"(v));
}

// ---------------- software grid barrier (all NBLK blocks co-resident) --------
__device__ __forceinline__ void gbar(unsigned phase) {
    __syncthreads();
    if (threadIdx.x == 0) {
        __threadfence();
        atomicAdd(&g_cnt, 1u);
        unsigned target = NBLK * phase;
        while (*(volatile unsigned*)&g_cnt < target) __nanosleep(64);
        __threadfence();
    }
    __syncthreads();
}

// ---------------- K1: persistent pipeline kernel -----------------------------
__global__ void __launch_bounds__(NTHR, 1) pipeline_kernel(
    const float* __restrict__ x, const int* __restrict__ ei, const int* __restrict__ cei,
    const float* __restrict__ W_ht, const float* __restrict__ b_ht,
    const float* __restrict__ W_lt, const float* __restrict__ b_lt,
    const float* __restrict__ Ws_h, const float* __restrict__ Wn_h,
    const float* __restrict__ b_h, const float* __restrict__ Ws_l,
    const float* __restrict__ Wn_l, const float* __restrict__ Wc_l,
    const float* __restrict__ b_l, const float* __restrict__ Whr,
    const float* __restrict__ bhr, const float* __restrict__ Wlr,
    const float* __restrict__ blr, const float* __restrict__ Wg,
    const float* __restrict__ bg, const float* __restrict__ ghn,
    const float* __restrict__ bhn, const float* __restrict__ gln,
    const float* __restrict__ bln, const float* __restrict__ ggn,
    const float* __restrict__ bgn, const float* __restrict__ Wa) {
    const int tid = threadIdx.x;
    const int bid = blockIdx.x;
    const int gtid = bid * NTHR + tid;
    __shared__ int s[256];

    // ===== Phase A: transpose x (gather layout) | count degrees | prep weights
    for (int i = gtid; i < 160832; i += TTHR) {
        if (i < 80000) {
            int b = i / NN;
            int n = i - b * NN;
            float v[12];
#pragma unroll
            for (int t = 0; t < Tt; t++) v[t] = x[((size_t)b * Tt + t) * NN + n];
            float4* dst = (float4*)(g_xT + (size_t)i * 16);
            dst[0] = make_float4(v[0], v[1], v[2], v[3]);
            dst[1] = make_float4(v[4], v[5], v[6], v[7]);
            dst[2] = make_float4(v[8], v[9], v[10], v[11]);
            dst[3] = make_float4(0.f, 0.f, 0.f, 0.f);
        } else if (i < 160000) {
            int q = i - 80000;
            if (q < 40000) {
                int4 v = ((const int4*)(ei + EE))[q];
                atomicAdd(&g_degN[v.x], 1);
                atomicAdd(&g_degN[v.y], 1);
                atomicAdd(&g_degN[v.z], 1);
                atomicAdd(&g_degN[v.w], 1);
            } else {
                int4 v = ((const int4*)(cei + EE))[q - 40000];
                atomicAdd(&g_degC[v.x], 1);
                atomicAdd(&g_degC[v.y], 1);
                atomicAdd(&g_degC[v.z], 1);
                atomicAdd(&g_degC[v.w], 1);
            }
        } else {
            int pid = i - 160000;  // 0..831
            int t = pid >> 6;
            int d = pid & 63;
            int dl = d & 31;
            int hi = d >> 5;
            if (t < Tt) {
                float s1 = 0.f, s2 = 0.f, s3 = 0.f, s4 = 0.f, s5 = 0.f;
                for (int k = 0; k < 64; k++) {
                    float wht = W_ht[t * 64 + k];
                    float wlt = W_lt[t * 64 + k];
                    s1 += wht * (Ws_h[k * 64 + d] + 0.2f * Whr[k * 64 + d]);
                    s2 += wht * Wn_h[k * 64 + d];
                    s3 += wlt * (Ws_l[k * 64 + d] + 0.2f * Wlr[k * 64 + d]);
                    s4 += wlt * Wn_l[k * 64 + d];
                    s5 += wlt * Wc_l[k * 64 + d];
                }
                float* Wf = (float*)g_W;
                int base = (t * 32 + dl) * 2 + hi;
                Wf[base] = s1;
                Wf[768 + base] = s2;
                Wf[1536 + base] = s3;
                Wf[2304 + base] = s4;
                Wf[3072 + base] = s5;
                Wf[3840 + base] = 2.0f * Wg[t * 64 + d];  // x_res = 2x
            } else {
                float bh0 = b_h[d] + 0.2f * bhr[d];
                float bhm = 0.f;
                float bl0 = b_l[d] + 0.2f * blr[d];
                float blm = 0.f, blc = 0.f;
                for (int k = 0; k < 64; k++) {
                    bh0 += b_ht[k] * (Ws_h[k * 64 + d] + 0.2f * Whr[k * 64 + d]);
                    bhm += b_ht[k] * Wn_h[k * 64 + d];
                    bl0 += b_lt[k] * (Ws_l[k * 64 + d] + 0.2f * Wlr[k * 64 + d]);
                    blm += b_lt[k] * Wn_l[k * 64 + d];
                    blc += b_lt[k] * Wc_l[k * 64 + d];
                }
                g_bH0[d] = bh0;
                g_bHm[d] = bhm;
                g_bL0[d] = bl0;
                g_bLm[d] = blm;
                g_bLc[d] = blc;
            }
        }
    }
    gbar(1);

    // ===== Phase B1: per-block partial sums of degrees
    {
        int base = bid * CHUNK;
        if (tid < 68)
            s[tid] = (base + tid < NN) ? g_degN[base + tid] : 0;
        else if (tid < 128)
            s[tid] = 0;
        else if (tid < 196)
            s[tid] = (base + tid - 128 < NN) ? g_degC[base + tid - 128] : 0;
        else if (tid < 256)
            s[tid] = 0;
        __syncthreads();
#pragma unroll
        for (int off = 64; off > 0; off >>= 1) {
            if (tid < off)
                s[tid] += s[tid + off];
            else if (tid >= 128 && tid < 128 + off)
                s[tid] += s[tid + off];
            __syncthreads();
        }
        if (tid == 0) g_psumN[bid] = s[0];
        if (tid == 128) g_psumC[bid] = s[128];
    }
    gbar(2);

    // ===== Phase B2: exclusive scan of 148 partials
    if (bid == 0 && tid < 64) {
        int lane = tid & 31;
        int* p = (tid < 32) ? g_psumN : g_psumC;
        int carry = 0;
        for (int k = 0; k < 5; k++) {
            int i = k * 32 + lane;
            int v = (i < NBLK) ? p[i] : 0;
            int inc = v;
#pragma unroll
            for (int o = 1; o < 32; o <<= 1) {
                int u = __shfl_up_sync(0xffffffffu, inc, o);
                if (lane >= o) inc += u;
            }
            if (i < NBLK) p[i] = carry + inc - v;
            carry += __shfl_sync(0xffffffffu, inc, 31);
        }
    }
    gbar(3);

    // ===== Phase B3: local inclusive scan -> row offsets
    {
        int base = bid * CHUNK;
        if (tid < 68)
            s[tid] = (base + tid < NN) ? g_degN[base + tid] : 0;
        else if (tid < 128)
            s[tid] = 0;
        else if (tid < 196)
            s[tid] = (base + tid - 128 < NN) ? g_degC[base + tid - 128] : 0;
        else if (tid < 256)
            s[tid] = 0;
        __syncthreads();
#pragma unroll
        for (int off = 1; off < 128; off <<= 1) {
            int v = 0;
            if (tid < 256 && (tid & 127) >= off) v = s[tid - off];
            __syncthreads();
            if (tid < 256) s[tid] += v;
            __syncthreads();
        }
        if (tid < 68) {
            int n = base + tid;
            if (n < NN) g_rowN[n + 1] = g_psumN[bid] + s[tid];
        } else if (tid >= 128 && tid < 196) {
            int n = base + tid - 128;
            if (n < NN) g_rowC[n + 1] = g_psumC[bid] + s[tid];
        }
        if (bid == 0 && tid == 0) {
            g_rowN[0] = 0;
            g_rowC[0] = 0;
        }
    }
    gbar(4);

    // ===== Phase C: fill CSR columns | pack epilogue constants
    for (int i = gtid; i < 2 * EE + 32; i += TTHR) {
        if (i < EE) {
            int dd = __ldg(&ei[EE + i]);
            int p = atomicAdd(&g_curN[dd], 1);
            g_colN[g_rowN[dd] + p] = __ldg(&ei[i]);
        } else if (i < 2 * EE) {
            int j = i - EE;
            int dd = __ldg(&cei[EE + j]);
            int p = atomicAdd(&g_curC[dd], 1);
            g_colC[g_rowC[dd] + p] = __ldg(&cei[j]);
        } else {
            int l = i - 2 * EE;  // 0..31
            float4* C = (float4*)g_Cpk;
            C[0 * 32 + l] = make_float4(g_bH0[l], g_bH0[l + 32], g_bHm[l], g_bHm[l + 32]);
            C[1 * 32 + l] = make_float4(g_bL0[l], g_bL0[l + 32], g_bLm[l], g_bLm[l + 32]);
            C[2 * 32 + l] = make_float4(g_bLc[l], g_bLc[l + 32], bg[l], bg[l + 32]);
            C[3 * 32 + l] = make_float4(ghn[l], ghn[l + 32], bhn[l], bhn[l + 32]);
            C[4 * 32 + l] = make_float4(gln[l], gln[l + 32], bln[l], bln[l + 32]);
            C[5 * 32 + l] = make_float4(ggn[l], ggn[l + 32], bgn[l], bgn[l + 32]);
            C[6 * 32 + l] =
                make_float4(Wa[l * 2], Wa[(l + 32) * 2], Wa[l * 2 + 1], Wa[(l + 32) * 2 + 1]);
            C[7 * 32 + l] = make_float4(Wa[(64 + l) * 2], Wa[(96 + l) * 2], Wa[(64 + l) * 2 + 1],
                                        Wa[(96 + l) * 2 + 1]);
        }
    }
    gbar(5);

    // ===== Phase D: gather-aggregate (compact [f][12]) + mflag + cleanup
    for (int idx = gtid; idx < 340000; idx += TTHR) {
        if (idx < 320000) {
            int t = idx & 15;
            if (t >= Tt) continue;
            int n = idx >> 4;
            int causal = (n >= NN);
            if (causal) n -= NN;
            const int* __restrict__ row = causal ? g_rowC : g_rowN;
            const int* __restrict__ col = causal ? g_colC : g_colN;
            float* __restrict__ dst = causal ? g_aggC : g_aggN;
            int rs = row[n], re = row[n + 1];
            float acc[Bx];
#pragma unroll
            for (int b = 0; b < Bx; b++) acc[b] = 0.f;
#pragma unroll 2
            for (int e = rs; e < re; e++) {
                int c = __ldg(&col[e]);
                const float* p = g_xT + c * 16 + t;
#pragma unroll
                for (int b = 0; b < Bx; b++) acc[b] += __ldg(&p[b * NN * 16]);
            }
            float invd = 1.0f / fmaxf((float)(re - rs), 1.0f);
#pragma unroll
            for (int b = 0; b < Bx; b++) dst[(size_t)(b * NN + n) * 12 + t] = acc[b] * invd;
        } else if (idx < 330000) {
            int z = idx - 320000;  // zero deg/cur (int4 granularity)
            int a = z / 2500;
            int r = z - a * 2500;
            int4 zv = make_int4(0, 0, 0, 0);
            if (a == 0)
                ((int4*)g_degN)[r] = zv;
            else if (a == 1)
                ((int4*)g_degC)[r] = zv;
            else if (a == 2)
                ((int4*)g_curN)[r] = zv;
            else
                ((int4*)g_curC)[r] = zv;
        } else {
            int n = idx - 330000;  // mflag from persistent row arrays
            g_mflag[n] = make_float2((g_rowN[n + 1] > g_rowN[n]) ? 1.f : 0.f,
                                     (g_rowC[n + 1] > g_rowC[n]) ? 1.f : 0.f);
        }
    }
}

// ---------------- K2: fused epilogue (thread-per-node, raw staging) -----------
// 64 thr/block, thread = one flat node. Pass A: compute hp/lp ONCE, write RAW
// values into the final high/low slots (coalesced along n) while accumulating
// LN stats; rp computed for stats only. Pass 2: read back raw (same thread,
// L2-hot), LN + activations in place, gate partials. Pass 3: recompute rp
// (cheapest bank), read high/low back, fuse. All weight LDS are warp-uniform
// LDS.128 broadcasts.
#define FB3 (FT / 64) /* 1250 blocks */

__global__ void __launch_bounds__(64, 8) final_kernel(float* __restrict__ out,
                                                      const float* __restrict__ x,
                                                      const float* __restrict__ ba) {
    const int tid = threadIdx.x;
    if (blockIdx.x == 0 && tid == 0) g_cnt = 0;  // reset grid barrier for next replay

    __shared__ ull sW[2304];    // 6 banks x 12 t x 32 pairs (18.4 KB)
    __shared__ float4 sC[256];  // 8 const banks x 32 pairs  (4 KB)
#pragma unroll
    for (int i = 0; i < 18; i++)
        ((ulonglong2*)sW)[tid + i * 64] = ((const ulonglong2*)g_W)[tid + i * 64];
#pragma unroll
    for (int i = 0; i < 4; i++) sC[tid + i * 64] = ((const float4*)g_Cpk)[tid + i * 64];
    __syncthreads();

    const int f = blockIdx.x * 64 + tid;
    const int b = f / NN;
    const int n = f - b * NN;
    const float ba0 = __ldg(&ba[0]), ba1 = __ldg(&ba[1]);
    const size_t AS = (size_t)Bx * OD * NN;
    const size_t obase = (size_t)(b * OD) * NN + n;
    float* __restrict__ pf = out + obase;           // fused slots
    float* __restrict__ ph = out + AS + obase;      // high slots
    float* __restrict__ pl = out + 2 * AS + obase;  // low slots

    // ---- features (held in registers across all passes)
    float vx[12], va[12], vc[12];
#pragma unroll
    for (int t = 0; t < Tt; t++) vx[t] = __ldg(&x[((size_t)b * Tt + t) * NN + n]);
    {
        const float4* pa = (const float4*)(g_aggN + (size_t)f * 12);
        const float4* pc = (const float4*)(g_aggC + (size_t)f * 12);
#pragma unroll
        for (int k = 0; k < 3; k++) {
            float4 a4 = __ldg(&pa[k]);
            float4 c4 = __ldg(&pc[k]);
            va[4 * k] = a4.x;
            va[4 * k + 1] = a4.y;
            va[4 * k + 2] = a4.z;
            va[4 * k + 3] = a4.w;
            vc[4 * k] = c4.x;
            vc[4 * k + 1] = c4.y;
            vc[4 * k + 2] = c4.z;
            vc[4 * k + 3] = c4.w;
        }
    }
    float2 mf = __ldg(&g_mflag[n]);
    const ull pkm = PK2(mf.x, mf.x), pkmc = PK2(mf.y, mf.y);

    // ================= pass A: single GEMV, raw staging + stats ===============
    ull aH = 0, aH2 = 0, aL = 0, aL2 = 0, aR = 0, aR2 = 0;
#pragma unroll 1
    for (int c = 0; c < 4; c++) {  // hp: banks 0,1 -> raw to high slots
        int p0 = c * 8;
        ull acc[8];
#pragma unroll
        for (int j = 0; j < 8; j++) {
            float4 c0 = sC[p0 + j];
            acc[j] = PK2(c0.x, c0.y);
            FMA2(acc[j], pkm, PK2(c0.z, c0.w));
        }
#pragma unroll
        for (int t = 0; t < Tt; t++) {
            ull qx = PK2(vx[t], vx[t]), qa = PK2(va[t], va[t]);
            const ulonglong2* w0 = (const ulonglong2*)(sW + t * 32 + p0);
            const ulonglong2* w1 = (const ulonglong2*)(sW + 384 + t * 32 + p0);
#pragma unroll
            for (int j = 0; j < 4; j++) {
                ulonglong2 u0 = w0[j], u1 = w1[j];
                FMA2(acc[2 * j], qx, u0.x);
                FMA2(acc[2 * j + 1], qx, u0.y);
                FMA2(acc[2 * j], qa, u1.x);
                FMA2(acc[2 * j + 1], qa, u1.y);
            }
        }
#pragma unroll
        for (int j = 0; j < 8; j++) {
            int p = p0 + j;
            ADD2(aH, acc[j]);
            FMA2(aH2, acc[j], acc[j]);
            float hl, hh;
            UPK2(hl, hh, acc[j]);
            ph[(size_t)p * NN] = hl;
            ph[(size_t)(p + 32) * NN] = hh;
        }
    }
#pragma unroll 1
    for (int c = 0; c < 4; c++) {  // lp: banks 2,3,4 -> raw to low slots
        int p0 = c * 8;
        ull acc[8];
#pragma unroll
        for (int j = 0; j < 8; j++) {
            float4 c1 = sC[32 + p0 + j];
            float4 c2 = sC[64 + p0 + j];
            acc[j] = PK2(c1.x, c1.y);
            FMA2(acc[j], pkm, PK2(c1.z, c1.w));
            FMA2(acc[j], pkmc, PK2(c2.x, c2.y));
        }
#pragma unroll
        for (int t = 0; t < Tt; t++) {
            ull qx = PK2(vx[t], vx[t]), qa = PK2(va[t], va[t]), qc = PK2(vc[t], vc[t]);
            const ulonglong2* w2 = (const ulonglong2*)(sW + 768 + t * 32 + p0);
            const ulonglong2* w3 = (const ulonglong2*)(sW + 1152 + t * 32 + p0);
            const ulonglong2* w4 = (const ulonglong2*)(sW + 1536 + t * 32 + p0);
#pragma unroll
            for (int j = 0; j < 4; j++) {
                ulonglong2 u2 = w2[j], u3 = w3[j], u4 = w4[j];
                FMA2(acc[2 * j], qx, u2.x);
                FMA2(acc[2 * j + 1], qx, u2.y);
                FMA2(acc[2 * j], qa, u3.x);
                FMA2(acc[2 * j + 1], qa, u3.y);
                FMA2(acc[2 * j], qc, u4.x);
                FMA2(acc[2 * j + 1], qc, u4.y);
            }
        }
#pragma unroll
        for (int j = 0; j < 8; j++) {
            int p = p0 + j;
            ADD2(aL, acc[j]);
            FMA2(aL2, acc[j], acc[j]);
            float ll, lh;
            UPK2(ll, lh, acc[j]);
            pl[(size_t)p * NN] = ll;
            pl[(size_t)(p + 32) * NN] = lh;
        }
    }
#pragma unroll 1
    for (int c = 0; c < 4; c++) {  // rp: bank 5 (stats only)
        int p0 = c * 8;
        ull acc[8];
#pragma unroll
        for (int j = 0; j < 8; j++) {
            float4 c2 = sC[64 + p0 + j];
            acc[j] = PK2(c2.z, c2.w);
        }
#pragma unroll
        for (int t = 0; t < Tt; t++) {
            ull qx = PK2(vx[t], vx[t]);
            const ulonglong2* w5 = (const ulonglong2*)(sW + 1920 + t * 32 + p0);
#pragma unroll
            for (int j = 0; j < 4; j++) {
                ulonglong2 u5 = w5[j];
                FMA2(acc[2 * j], qx, u5.x);
                FMA2(acc[2 * j + 1], qx, u5.y);
            }
        }
#pragma unroll
        for (int j = 0; j < 8; j++) {
            ADD2(aR, acc[j]);
            FMA2(aR2, acc[j], acc[j]);
        }
    }
    const float inv = 1.0f / 64.0f;
    float u0, u1;
    UPK2(u0, u1, aH);
    float mh = (u0 + u1) * inv;
    UPK2(u0, u1, aH2);
    float vh = (u0 + u1) * inv - mh * mh;
    UPK2(u0, u1, aL);
    float ml = (u0 + u1) * inv;
    UPK2(u0, u1, aL2);
    float vl = (u0 + u1) * inv - ml * ml;
    UPK2(u0, u1, aR);
    float mr = (u0 + u1) * inv;
    UPK2(u0, u1, aR2);
    float vr = (u0 + u1) * inv - mr * mr;
    float rhv = rsqrtf(vh + 1e-5f), rlv = rsqrtf(vl + 1e-5f), rrv = rsqrtf(vr + 1e-5f);

    // ================= pass 2: read raw, transform in place, gate =============
    float z0 = 0.f, z1 = 0.f;
#pragma unroll 4
    for (int p = 0; p < 32; p++) {
        float4 c3 = sC[96 + p], c4 = sC[128 + p], c6 = sC[192 + p], c7 = sC[224 + p];
        float hl = ph[(size_t)p * NN], hh = ph[(size_t)(p + 32) * NN];
        float ll = pl[(size_t)p * NN], lh = pl[(size_t)(p + 32) * NN];
        float highl = fmaf((hl - mh) * rhv, c3.x, c3.z);
        float highh = fmaf((hh - mh) * rhv, c3.y, c3.w);
        highl = (highl >= 0.f) ? highl : 0.1f * highl;
        highh = (highh >= 0.f) ? highh : 0.1f * highh;
        float lwl = fmaf((ll - ml) * rlv, c4.x, c4.z);
        float lwh = fmaf((lh - ml) * rlv, c4.y, c4.w);
        float lowl = 0.5f * lwl * (1.0f + erff(lwl * 0.70710678118654752f));
        float lowh = 0.5f * lwh * (1.0f + erff(lwh * 0.70710678118654752f));
        z0 += highl * c6.x + highh * c6.y + lowl * c7.x + lowh * c7.y;
        z1 += highl * c6.z + highh * c6.w + lowl * c7.z + lowh * c7.w;
        ph[(size_t)p * NN] = highl;
        ph[(size_t)(p + 32) * NN] = highh;
        pl[(size_t)p * NN] = lowl;
        pl[(size_t)(p + 32) * NN] = lowh;
    }
    float a0 = 1.0f / (1.0f + expf((z1 + ba1) - (z0 + ba0)));
    float a1 = 1.0f - a0;

    // ================= pass 3: rp recompute + read-back + fuse ================
#pragma unroll 1
    for (int c = 0; c < 4; c++) {
        int p0 = c * 8;
        ull acc[8];
#pragma unroll
        for (int j = 0; j < 8; j++) {
            float4 c2 = sC[64 + p0 + j];
            acc[j] = PK2(c2.z, c2.w);
        }
#pragma unroll
        for (int t = 0; t < Tt; t++) {
            ull qx = PK2(vx[t], vx[t]);
            const ulonglong2* w5 = (const ulonglong2*)(sW + 1920 + t * 32 + p0);
#pragma unroll
            for (int j = 0; j < 4; j++) {
                ulonglong2 u5 = w5[j];
                FMA2(acc[2 * j], qx, u5.x);
                FMA2(acc[2 * j + 1], qx, u5.y);
            }
        }
#pragma unroll
        for (int j = 0; j < 8; j++) {
            int p = p0 + j;
            float4 c5 = sC[160 + p];
            float rl, rh;
            UPK2(rl, rh, acc[j]);
            float resl = fmaf((rl - mr) * rrv, c5.x, c5.z);
            float resh = fmaf((rh - mr) * rrv, c5.y, c5.w);
            float hl = ph[(size_t)p * NN], hh = ph[(size_t)(p + 32) * NN];
            float ll = pl[(size_t)p * NN], lh = pl[(size_t)(p + 32) * NN];
            float fl = fmaf(a0, hl, a1 * ll) + 0.3f * (hl + ll) + 0.1f * resl;
            float fh = fmaf(a0, hh, a1 * lh) + 0.3f * (hh + lh) + 0.1f * resh;
            pf[(size_t)p * NN] = fl;
            pf[(size_t)(p + 32) * NN] = fh;
        }
    }
}

// ---------------- launch ------------------------------------------------------

extern "C" void kernel_launch(void* const* d_in, const int* in_sizes, int n_in, void* d_out,
                              int out_size) {
    const float* x = (const float*)d_in[0];
    const int* ei = (const int*)d_in[1];
    const int* cei = (const int*)d_in[2];
    const float* W_ht = (const float*)d_in[3];
    const float* b_ht = (const float*)d_in[4];
    const float* W_lt = (const float*)d_in[5];
    const float* b_lt = (const float*)d_in[6];
    const float* Ws_h = (const float*)d_in[7];
    const float* Wn_h = (const float*)d_in[8];
    const float* b_h = (const float*)d_in[9];
    const float* Ws_l = (const float*)d_in[10];
    const float* Wn_l = (const float*)d_in[11];
    const float* Wc_l = (const float*)d_in[12];
    const float* b_l = (const float*)d_in[13];
    const float* Whr = (const float*)d_in[14];
    const float* bhr = (const float*)d_in[15];
    const float* Wlr = (const float*)d_in[16];
    const float* blr = (const float*)d_in[17];
    const float* ghn = (const float*)d_in[18];
    const float* bhn = (const float*)d_in[19];
    const float* gln = (const float*)d_in[20];
    const float* bln = (const float*)d_in[21];
    const float* Wa = (const float*)d_in[22];
    const float* ba = (const float*)d_in[23];
    const float* Wg = (const float*)d_in[24];
    const float* bg = (const float*)d_in[25];
    const float* ggn = (const float*)d_in[26];
    const float* bgn = (const float*)d_in[27];
    float* out = (float*)d_out;

    pipeline_kernel<<<NBLK, NTHR>>>(x, ei, cei, W_ht, b_ht, W_lt, b_lt, Ws_h, Wn_h, b_h, Ws_l,
                                    Wn_l, Wc_l, b_l, Whr, bhr, Wlr, blr, Wg, bg, ghn, bhn, gln,
                                    bln, ggn, bgn, Wa);
    final_kernel<<<FB3, 64>>>(out, x, ba);
}